// round 2
// baseline (speedup 1.0000x reference)
#include <cuda_runtime.h>
#include <cstdint>

// Problem constants
#define BB 4
#define TT 1024
#define DD 1024
#define HH 16
#define HD 64
#define SC 3072
#define SF 4096   // full seq = SC + TT

// Scratch (device globals: no allocation allowed)
__device__ float g_q[(size_t)BB * HH * TT * HD];   // q, scaled by hd^-0.5, layout [b,h,t,hd]
__device__ float g_attn[(size_t)BB * TT * DD];     // attention output, layout [b,t,d]

// ---------------------------------------------------------------------------
// 128x128 SGEMM core: C(128x128) = A[M=4096,K=1024] * W[K=1024,N=1024]
// 256 threads, 8x8 per thread, BK=8.
// ---------------------------------------------------------------------------
__device__ __forceinline__ void gemm128(const float* __restrict__ A,
                                        const float* __restrict__ W,
                                        float acc[8][8])
{
    __shared__ float As[8][128];
    __shared__ float Bs[8][128];

    const int tid   = threadIdx.x;
    const int row_a = tid >> 1;          // 0..127
    const int col_a = (tid & 1) << 2;    // 0 or 4
    const int row_b = tid >> 5;          // 0..7
    const int col_b = (tid & 31) << 2;   // 0..124
    const int tx    = (tid & 15) << 3;   // 0..120
    const int ty    = (tid >> 4) << 3;   // 0..120
    const int bm    = blockIdx.y * 128;
    const int bn    = blockIdx.x * 128;

    const float* Aptr = A + (size_t)(bm + row_a) * 1024 + col_a;
    const float* Wptr = W + (size_t)row_b * 1024 + bn + col_b;

    for (int k0 = 0; k0 < 1024; k0 += 8) {
        float4 av = *(const float4*)(Aptr + k0);
        float4 wv = *(const float4*)(Wptr + (size_t)k0 * 1024);
        As[col_a + 0][row_a] = av.x;
        As[col_a + 1][row_a] = av.y;
        As[col_a + 2][row_a] = av.z;
        As[col_a + 3][row_a] = av.w;
        *(float4*)&Bs[row_b][col_b] = wv;
        __syncthreads();

        #pragma unroll
        for (int kk = 0; kk < 8; kk++) {
            float ra[8], rb[8];
            *(float4*)&ra[0] = *(const float4*)&As[kk][ty];
            *(float4*)&ra[4] = *(const float4*)&As[kk][ty + 4];
            *(float4*)&rb[0] = *(const float4*)&Bs[kk][tx];
            *(float4*)&rb[4] = *(const float4*)&Bs[kk][tx + 4];
            #pragma unroll
            for (int i = 0; i < 8; i++)
                #pragma unroll
                for (int j = 0; j < 8; j++)
                    acc[i][j] += ra[i] * rb[j];
        }
        __syncthreads();
    }
}

// ---------------------------------------------------------------------------
// QKV projections. blockIdx.z: 0 = Q (scaled, scattered to g_q),
// 1 = K (no bias, into kout rows 3072..4095), 2 = V (bias, into vout).
// ---------------------------------------------------------------------------
__global__ __launch_bounds__(256) void qkv_gemm(
    const float* __restrict__ x,
    const float* __restrict__ Wq, const float* __restrict__ Wk, const float* __restrict__ Wv,
    const float* __restrict__ bq, const float* __restrict__ bv,
    float* __restrict__ kout, float* __restrict__ vout)
{
    const float* W = (blockIdx.z == 0) ? Wq : ((blockIdx.z == 1) ? Wk : Wv);
    float acc[8][8];
    #pragma unroll
    for (int i = 0; i < 8; i++)
        #pragma unroll
        for (int j = 0; j < 8; j++) acc[i][j] = 0.0f;

    gemm128(x, W, acc);

    const int tid = threadIdx.x;
    const int tx  = (tid & 15) << 3;
    const int ty  = (tid >> 4) << 3;
    const int bm  = blockIdx.y * 128;
    const int bn  = blockIdx.x * 128;

    if (blockIdx.z == 0) {
        // Q: scale by 64^-0.5 = 0.125, scatter to [b,h,t,hd]
        #pragma unroll
        for (int i = 0; i < 8; i++) {
            int m = bm + ty + i;
            int b = m >> 10, t = m & 1023;
            #pragma unroll
            for (int jq = 0; jq < 2; jq++) {
                int n  = bn + tx + jq * 4;
                int h  = n >> 6, hd = n & 63;
                float4 bias4 = *(const float4*)&bq[n];
                float4 v;
                v.x = (acc[i][jq * 4 + 0] + bias4.x) * 0.125f;
                v.y = (acc[i][jq * 4 + 1] + bias4.y) * 0.125f;
                v.z = (acc[i][jq * 4 + 2] + bias4.z) * 0.125f;
                v.w = (acc[i][jq * 4 + 3] + bias4.w) * 0.125f;
                *(float4*)&g_q[((size_t)((b << 4) + h) * 1024 + t) * 64 + hd] = v;
            }
        }
    } else {
        float* dst = (blockIdx.z == 1) ? kout : vout;
        const bool hasb = (blockIdx.z == 2);
        #pragma unroll
        for (int i = 0; i < 8; i++) {
            int m   = bm + ty + i;
            int row = (m >> 10) * SF + SC + (m & 1023);
            #pragma unroll
            for (int jq = 0; jq < 2; jq++) {
                int n = bn + tx + jq * 4;
                float4 bias4 = hasb ? *(const float4*)&bv[n] : make_float4(0.f, 0.f, 0.f, 0.f);
                float4 v;
                v.x = acc[i][jq * 4 + 0] + bias4.x;
                v.y = acc[i][jq * 4 + 1] + bias4.y;
                v.z = acc[i][jq * 4 + 2] + bias4.z;
                v.w = acc[i][jq * 4 + 3] + bias4.w;
                *(float4*)&dst[(size_t)row * 1024 + n] = v;
            }
        }
    }
}

// ---------------------------------------------------------------------------
// Output projection: out = g_attn @ Wo + bo
// ---------------------------------------------------------------------------
__global__ __launch_bounds__(256) void o_gemm(
    const float* __restrict__ Wo, const float* __restrict__ bo, float* __restrict__ out)
{
    float acc[8][8];
    #pragma unroll
    for (int i = 0; i < 8; i++)
        #pragma unroll
        for (int j = 0; j < 8; j++) acc[i][j] = 0.0f;

    gemm128(g_attn, Wo, acc);

    const int tid = threadIdx.x;
    const int tx  = (tid & 15) << 3;
    const int ty  = (tid >> 4) << 3;
    const int bm  = blockIdx.y * 128;
    const int bn  = blockIdx.x * 128;

    #pragma unroll
    for (int i = 0; i < 8; i++) {
        int m = bm + ty + i;
        #pragma unroll
        for (int jq = 0; jq < 2; jq++) {
            int n = bn + tx + jq * 4;
            float4 bias4 = *(const float4*)&bo[n];
            float4 v;
            v.x = acc[i][jq * 4 + 0] + bias4.x;
            v.y = acc[i][jq * 4 + 1] + bias4.y;
            v.z = acc[i][jq * 4 + 2] + bias4.z;
            v.w = acc[i][jq * 4 + 3] + bias4.w;
            *(float4*)&out[(size_t)m * 1024 + n] = v;
        }
    }
}

// ---------------------------------------------------------------------------
// Copy k_cache/v_cache into first SC rows of k/v outputs (float4 vectorized)
// ---------------------------------------------------------------------------
__global__ void copy_cache(const float4* __restrict__ kc, const float4* __restrict__ vc,
                           float4* __restrict__ ko, float4* __restrict__ vo)
{
    int idx = blockIdx.x * 256 + threadIdx.x;
    const int per_b = SC * 256;           // float4 per batch
    if (idx >= BB * per_b) return;
    int b = idx / per_b;
    int r = idx - b * per_b;
    int o = b * (SF * 256) + r;
    ko[o] = kc[idx];
    vo[o] = vc[idx];
}

// ---------------------------------------------------------------------------
// Flash-style attention.
// Grid: (qtile=16, h=16, b=4); 256 threads.
// Score tile 64(q) x 64(k); thread (tx,ty) 4x4 micro-tile; online softmax.
// Mask faithful to reference: key s masked iff s < 1024 AND s > t.
// ---------------------------------------------------------------------------
__global__ __launch_bounds__(256) void attn_kernel(
    const float* __restrict__ kfull, const float* __restrict__ vfull)
{
    extern __shared__ float sm[];
    float* Qs = sm;              // [64][68], d-major: Qs[d*68+i]
    float* Ks = Qs + 64 * 68;    // [64][68], d-major: Ks[d*68+j]
    float* Vs = Ks + 64 * 68;    // [64][68], j-major: Vs[j*68+d]
    float* Ps = Vs + 64 * 68;    // [64][68], j-major: Ps[j*68+i]

    const int tid = threadIdx.x;
    const int tx  = tid & 15;
    const int ty  = tid >> 4;
    const int qi  = blockIdx.x;
    const int h   = blockIdx.y;
    const int b   = blockIdx.z;
    const int qbase = qi * 64;

    // Load Q (pre-scaled), transposed to d-major
    const float* qsrc = g_q + ((size_t)(b * HH + h) * 1024 + qbase) * 64;
    for (int idx = tid; idx < 4096; idx += 256) {
        int i = idx >> 6, d = idx & 63;
        Qs[d * 68 + i] = qsrc[idx];
    }

    float m[4], l[4], O[4][4];
    #pragma unroll
    for (int i = 0; i < 4; i++) {
        m[i] = -1e30f; l[i] = 0.0f;
        #pragma unroll
        for (int j = 0; j < 4; j++) O[i][j] = 0.0f;
    }

    const float* kb = kfull + (size_t)b * SF * 1024 + h * 64;
    const float* vb = vfull + (size_t)b * SF * 1024 + h * 64;

    for (int si = 0; si < 64; si++) {
        // Fully-masked tiles (strictly above diagonal, within first 1024 cols): skip
        if (si < 16 && si > qi) continue;
        const int sbase = si * 64;

        __syncthreads();   // previous iteration's reads of Ks/Vs/Ps complete
        // Load K (d-major) + V (j-major)
        for (int idx = tid; idx < 1024; idx += 256) {
            int j  = idx >> 4;
            int dq = (idx & 15) << 2;
            float4 kv = *(const float4*)&kb[(size_t)(sbase + j) * 1024 + dq];
            Ks[(dq + 0) * 68 + j] = kv.x;
            Ks[(dq + 1) * 68 + j] = kv.y;
            Ks[(dq + 2) * 68 + j] = kv.z;
            Ks[(dq + 3) * 68 + j] = kv.w;
            float4 vv = *(const float4*)&vb[(size_t)(sbase + j) * 1024 + dq];
            *(float4*)&Vs[j * 68 + dq] = vv;
        }
        __syncthreads();

        // Scores S = Q K^T  (4x4 per thread)
        float s[4][4];
        #pragma unroll
        for (int i = 0; i < 4; i++)
            #pragma unroll
            for (int j = 0; j < 4; j++) s[i][j] = 0.0f;

        #pragma unroll 4
        for (int d = 0; d < 64; d++) {
            float4 rq4 = *(const float4*)&Qs[d * 68 + (ty << 2)];
            float4 rk4 = *(const float4*)&Ks[d * 68 + (tx << 2)];
            float rq[4] = {rq4.x, rq4.y, rq4.z, rq4.w};
            float rk[4] = {rk4.x, rk4.y, rk4.z, rk4.w};
            #pragma unroll
            for (int i = 0; i < 4; i++)
                #pragma unroll
                for (int j = 0; j < 4; j++)
                    s[i][j] += rq[i] * rk[j];
        }

        // Diagonal tile mask: j > i (same 64-block, sbase == qbase)
        if (si == qi) {
            #pragma unroll
            for (int i = 0; i < 4; i++)
                #pragma unroll
                for (int j = 0; j < 4; j++)
                    if ((tx << 2) + j > (ty << 2) + i) s[i][j] = -1e30f;
        }

        // Online softmax (row groups = 16 consecutive lanes)
        #pragma unroll
        for (int i = 0; i < 4; i++) {
            float mt = fmaxf(fmaxf(s[i][0], s[i][1]), fmaxf(s[i][2], s[i][3]));
            mt = fmaxf(mt, __shfl_xor_sync(0xffffffffu, mt, 1));
            mt = fmaxf(mt, __shfl_xor_sync(0xffffffffu, mt, 2));
            mt = fmaxf(mt, __shfl_xor_sync(0xffffffffu, mt, 4));
            mt = fmaxf(mt, __shfl_xor_sync(0xffffffffu, mt, 8));
            float mn    = fmaxf(m[i], mt);
            float alpha = __expf(m[i] - mn);
            m[i] = mn;
            float rs = 0.0f;
            #pragma unroll
            for (int j = 0; j < 4; j++) {
                float p = __expf(s[i][j] - mn);
                s[i][j] = p;
                rs += p;
            }
            rs += __shfl_xor_sync(0xffffffffu, rs, 1);
            rs += __shfl_xor_sync(0xffffffffu, rs, 2);
            rs += __shfl_xor_sync(0xffffffffu, rs, 4);
            rs += __shfl_xor_sync(0xffffffffu, rs, 8);
            l[i] = l[i] * alpha + rs;
            #pragma unroll
            for (int d = 0; d < 4; d++) O[i][d] *= alpha;
        }

        // Stage P (j-major) for the PV GEMM
        #pragma unroll
        for (int i = 0; i < 4; i++)
            #pragma unroll
            for (int j = 0; j < 4; j++)
                Ps[((tx << 2) + j) * 68 + (ty << 2) + i] = s[i][j];
        __syncthreads();

        // O += P V
        #pragma unroll 4
        for (int j = 0; j < 64; j++) {
            float4 rp4 = *(const float4*)&Ps[j * 68 + (ty << 2)];
            float4 rv4 = *(const float4*)&Vs[j * 68 + (tx << 2)];
            float rp[4] = {rp4.x, rp4.y, rp4.z, rp4.w};
            float rv[4] = {rv4.x, rv4.y, rv4.z, rv4.w};
            #pragma unroll
            for (int i = 0; i < 4; i++)
                #pragma unroll
                for (int d = 0; d < 4; d++)
                    O[i][d] += rp[i] * rv[d];
        }
    }

    // Epilogue: normalize and write to g_attn [b,t,d]
    #pragma unroll
    for (int i = 0; i < 4; i++) {
        float inv = 1.0f / l[i];
        float4 ov;
        ov.x = O[i][0] * inv;
        ov.y = O[i][1] * inv;
        ov.z = O[i][2] * inv;
        ov.w = O[i][3] * inv;
        size_t row = (size_t)b * 1024 + qbase + (ty << 2) + i;
        *(float4*)&g_attn[row * 1024 + h * 64 + (tx << 2)] = ov;
    }
}

// ---------------------------------------------------------------------------
extern "C" void kernel_launch(void* const* d_in, const int* in_sizes, int n_in,
                              void* d_out, int out_size)
{
    const float* x  = (const float*)d_in[0];
    const float* kc = (const float*)d_in[1];
    const float* vc = (const float*)d_in[2];
    const float* Wq = (const float*)d_in[3];
    const float* bq = (const float*)d_in[4];
    const float* Wk = (const float*)d_in[5];
    const float* Wv = (const float*)d_in[6];
    const float* bv = (const float*)d_in[7];
    const float* Wo = (const float*)d_in[8];
    const float* bo = (const float*)d_in[9];

    float* out  = (float*)d_out;                         // [4,1024,1024]
    float* kout = out + (size_t)BB * TT * DD;            // [4,4096,1024]
    float* vout = kout + (size_t)BB * SF * DD;           // [4,4096,1024]

    const int attn_smem = 4 * 64 * 68 * (int)sizeof(float);  // 69632 B
    cudaFuncSetAttribute(attn_kernel, cudaFuncAttributeMaxDynamicSharedMemorySize, attn_smem);

    // 1. cache copy (independent of GEMMs)
    {
        int total = BB * SC * 256;  // float4 count
        copy_cache<<<(total + 255) / 256, 256>>>(
            (const float4*)kc, (const float4*)vc, (float4*)kout, (float4*)vout);
    }
    // 2. fused QKV projections
    qkv_gemm<<<dim3(8, 32, 3), 256>>>(x, Wq, Wk, Wv, bq, bv, kout, vout);
    // 3. attention (reads kout/vout incl. new rows)
    attn_kernel<<<dim3(16, 16, 4), 256, attn_smem>>>(kout, vout);
    // 4. output projection
    o_gemm<<<dim3(8, 32), 256>>>(Wo, bo, out);
}

// round 3
// speedup vs baseline: 2.4728x; 2.4728x over previous
#include <cuda_runtime.h>
#include <cuda_bf16.h>
#include <cstdint>

#define BB 4
#define TT 1024
#define DD 1024
#define HH 16
#define HD 64
#define SC 3072
#define SF 4096

typedef __nv_bfloat16 bf16;
typedef __nv_bfloat162 bf162;

__device__ bf16 g_xh[(size_t)BB * TT * DD];
__device__ bf16 g_xl[(size_t)BB * TT * DD];
__device__ bf16 g_wth[4ull * DD * DD];
__device__ bf16 g_wtl[4ull * DD * DD];
__device__ float g_qf[(size_t)BB * HH * TT * HD];
__device__ bf16 g_qh[(size_t)BB * HH * TT * HD];
__device__ bf16 g_ql[(size_t)BB * HH * TT * HD];
__device__ bf16 g_kh[(size_t)BB * HH * SF * HD];
__device__ bf16 g_kl[(size_t)BB * HH * SF * HD];
__device__ bf16 g_vth[(size_t)BB * HH * HD * SF];
__device__ bf16 g_vtl[(size_t)BB * HH * HD * SF];
__device__ bf16 g_ah[(size_t)BB * TT * DD];
__device__ bf16 g_al[(size_t)BB * TT * DD];

__device__ __forceinline__ uint32_t smem_u32(const void* p) {
    return (uint32_t)__cvta_generic_to_shared(p);
}
__device__ __forceinline__ void ldsm4(uint32_t (&r)[4], const void* p) {
    asm volatile("ldmatrix.sync.aligned.m8n8.x4.shared.b16 {%0,%1,%2,%3}, [%4];"
        : "=r"(r[0]), "=r"(r[1]), "=r"(r[2]), "=r"(r[3]) : "r"(smem_u32(p)));
}
__device__ __forceinline__ void mma16816(float (&c)[4], const uint32_t (&a)[4],
                                         uint32_t b0, uint32_t b1) {
    asm volatile(
        "mma.sync.aligned.m16n8k16.row.col.f32.bf16.bf16.f32 "
        "{%0,%1,%2,%3},{%4,%5,%6,%7},{%8,%9},{%0,%1,%2,%3};"
        : "+f"(c[0]), "+f"(c[1]), "+f"(c[2]), "+f"(c[3])
        : "r"(a[0]), "r"(a[1]), "r"(a[2]), "r"(a[3]), "r"(b0), "r"(b1));
}
__device__ __forceinline__ void split1(float v, bf16& h, bf16& l) {
    h = __float2bfloat16(v);
    l = __float2bfloat16(v - __bfloat162float(h));
}
__device__ __forceinline__ void split_pack(float x, float y, uint32_t& ph, uint32_t& pl) {
    bf162 H, L;
    split1(x, H.x, L.x); split1(y, H.y, L.y);
    ph = *reinterpret_cast<uint32_t*>(&H);
    pl = *reinterpret_cast<uint32_t*>(&L);
}

// ---------------- conversions -------------------------------------------------
__global__ void conv_x(const float4* __restrict__ x) {
    int i = blockIdx.x * 256 + threadIdx.x;
    float4 v = x[i];
    bf162 h01, l01, h23, l23;
    split1(v.x, h01.x, l01.x); split1(v.y, h01.y, l01.y);
    split1(v.z, h23.x, l23.x); split1(v.w, h23.y, l23.y);
    reinterpret_cast<bf162*>(g_xh)[2 * i]     = h01;
    reinterpret_cast<bf162*>(g_xh)[2 * i + 1] = h23;
    reinterpret_cast<bf162*>(g_xl)[2 * i]     = l01;
    reinterpret_cast<bf162*>(g_xl)[2 * i + 1] = l23;
}

__global__ void conv_q() {
    int i = blockIdx.x * 256 + threadIdx.x;
    float4 v = reinterpret_cast<const float4*>(g_qf)[i];
    bf162 h01, l01, h23, l23;
    split1(v.x, h01.x, l01.x); split1(v.y, h01.y, l01.y);
    split1(v.z, h23.x, l23.x); split1(v.w, h23.y, l23.y);
    reinterpret_cast<bf162*>(g_qh)[2 * i]     = h01;
    reinterpret_cast<bf162*>(g_qh)[2 * i + 1] = h23;
    reinterpret_cast<bf162*>(g_ql)[2 * i]     = l01;
    reinterpret_cast<bf162*>(g_ql)[2 * i + 1] = l23;
}

__global__ void conv_w(const float* __restrict__ Wq, const float* __restrict__ Wk,
                       const float* __restrict__ Wv, const float* __restrict__ Wo) {
    __shared__ float t[32][33];
    int z = blockIdx.z;
    const float* W = (z == 0) ? Wq : (z == 1) ? Wk : (z == 2) ? Wv : Wo;
    int n0 = blockIdx.x * 32, k0 = blockIdx.y * 32;
    int tx = threadIdx.x, ty = threadIdx.y;
    #pragma unroll
    for (int r = 0; r < 32; r += 8)
        t[ty + r][tx] = W[(size_t)(k0 + ty + r) * DD + n0 + tx];
    __syncthreads();
    size_t base = (size_t)z * DD * DD;
    #pragma unroll
    for (int r = 0; r < 32; r += 8) {
        bf16 h, l; split1(t[tx][ty + r], h, l);
        size_t o = base + (size_t)(n0 + ty + r) * DD + k0 + tx;
        g_wth[o] = h; g_wtl[o] = l;
    }
}

// K rows -> [b,h,s,d] bf16 hi/lo (+ optional fp32 copy into kout)
__global__ void conv_k(const float4* __restrict__ src, size_t sbs4, int s0, int ns,
                       float4* __restrict__ kout4) {
    int i = blockIdx.x * 256 + threadIdx.x;
    int per_b = ns * 256;
    int b = i / per_b, r = i - b * per_b;
    int sr = r >> 8, n4 = r & 255;
    float4 v = src[(size_t)b * sbs4 + (size_t)sr * 256 + n4];
    if (kout4) kout4[((size_t)b * SF + s0 + sr) * 256 + n4] = v;
    int n = n4 * 4, h = n >> 6, d = n & 63;
    size_t o = ((size_t)(b * HH + h) * SF + s0 + sr) * HD + d;
    bf162 h01, l01, h23, l23;
    split1(v.x, h01.x, l01.x); split1(v.y, h01.y, l01.y);
    split1(v.z, h23.x, l23.x); split1(v.w, h23.y, l23.y);
    *reinterpret_cast<bf162*>(&g_kh[o])     = h01;
    *reinterpret_cast<bf162*>(&g_kh[o + 2]) = h23;
    *reinterpret_cast<bf162*>(&g_kl[o])     = l01;
    *reinterpret_cast<bf162*>(&g_kl[o + 2]) = l23;
}

// V rows -> transposed [b,h,d,s] bf16 hi/lo (+ optional fp32 copy into vout)
__global__ void conv_vt(const float* __restrict__ src, size_t sbs, int s0, int ns,
                        float* __restrict__ vout) {
    __shared__ float t[32][33];
    int b = blockIdx.z;
    int h = blockIdx.y >> 1;
    int d0 = (blockIdx.y & 1) * 32;
    int st = blockIdx.x * 32;
    int tx = threadIdx.x, ty = threadIdx.y;
    #pragma unroll
    for (int r = 0; r < 32; r += 8) {
        float v = src[(size_t)b * sbs + (size_t)(st + ty + r) * DD + h * HD + d0 + tx];
        t[ty + r][tx] = v;
        if (vout) vout[((size_t)b * SF + s0 + st + ty + r) * DD + h * HD + d0 + tx] = v;
    }
    __syncthreads();
    #pragma unroll
    for (int r = 0; r < 32; r += 8) {
        bf16 hh, ll; split1(t[tx][ty + r], hh, ll);
        size_t o = ((size_t)(b * HH + h) * HD + d0 + ty + r) * SF + s0 + st + tx;
        g_vth[o] = hh; g_vtl[o] = ll;
    }
}

// ---------------- split-bf16 HMMA GEMM core (128x128 tile, 256 thr) ----------
__device__ __forceinline__ void gemm_core(const bf16* __restrict__ Ah, const bf16* __restrict__ Al,
                                          const bf16* __restrict__ Bh, const bf16* __restrict__ Bl,
                                          int bm, int bn, float (&c)[4][4][4]) {
    __shared__ __align__(16) bf16 As[2][128][24];
    __shared__ __align__(16) bf16 Bs[2][128][24];

    const int tid  = threadIdx.x;
    const int lane = tid & 31, wid = tid >> 5;
    const int wm = (wid & 1) * 64, wn = (wid >> 1) * 32;
    const int lr = tid >> 1, lc = (tid & 1) * 8;
    const int ar = lane & 15, akk = (lane >> 4) * 8;
    const int br = (lane & 7) + ((lane >> 4) << 3), bkk = ((lane >> 3) & 1) * 8;

    #pragma unroll
    for (int mt = 0; mt < 4; mt++)
        #pragma unroll
        for (int nt = 0; nt < 4; nt++)
            #pragma unroll
            for (int e = 0; e < 4; e++) c[mt][nt][e] = 0.0f;

    uint4 ra = *(const uint4*)(Ah + (size_t)(bm + lr) * DD + lc);
    uint4 rb = *(const uint4*)(Bh + (size_t)(bn + lr) * DD + lc);
    *(uint4*)&As[0][lr][lc] = ra;
    *(uint4*)&Bs[0][lr][lc] = rb;
    __syncthreads();

    int buf = 0;
    #pragma unroll 1
    for (int ch = 0; ch < 192; ch++) {
        if (ch < 191) {
            int c1 = ch + 1, sp = c1 >> 6, k0 = (c1 & 63) << 4;
            const bf16* Ap = (sp == 1) ? Al : Ah;
            const bf16* Bp = (sp == 2) ? Bl : Bh;
            ra = *(const uint4*)(Ap + (size_t)(bm + lr) * DD + k0 + lc);
            rb = *(const uint4*)(Bp + (size_t)(bn + lr) * DD + k0 + lc);
        }
        uint32_t a[4][4], bfr[2][4];
        #pragma unroll
        for (int mt = 0; mt < 4; mt++)
            ldsm4(a[mt], &As[buf][wm + mt * 16 + ar][akk]);
        #pragma unroll
        for (int np = 0; np < 2; np++)
            ldsm4(bfr[np], &Bs[buf][wn + np * 16 + br][bkk]);
        #pragma unroll
        for (int mt = 0; mt < 4; mt++)
            #pragma unroll
            for (int nt = 0; nt < 4; nt++) {
                int np = nt >> 1, pi = (nt & 1) * 2;
                mma16816(c[mt][nt], a[mt], bfr[np][pi], bfr[np][pi + 1]);
            }
        if (ch < 191) {
            *(uint4*)&As[buf ^ 1][lr][lc] = ra;
            *(uint4*)&Bs[buf ^ 1][lr][lc] = rb;
        }
        __syncthreads();
        buf ^= 1;
    }
}

__global__ __launch_bounds__(256) void gemm_qkv(const float* __restrict__ bq,
                                                const float* __restrict__ bv,
                                                float* __restrict__ kout,
                                                float* __restrict__ vout) {
    const int z = blockIdx.z;
    const int bm = blockIdx.y * 128, bn = blockIdx.x * 128;
    float c[4][4][4];
    gemm_core(g_xh, g_xl, g_wth + (size_t)z * DD * DD, g_wtl + (size_t)z * DD * DD, bm, bn, c);

    const int lane = threadIdx.x & 31, wid = threadIdx.x >> 5;
    const int wm = (wid & 1) * 64, wn = (wid >> 1) * 32;
    const int g = lane >> 2, tg = lane & 3;

    #pragma unroll
    for (int mt = 0; mt < 4; mt++)
        #pragma unroll
        for (int nt = 0; nt < 4; nt++)
            #pragma unroll
            for (int hf = 0; hf < 2; hf++) {
                int row = bm + wm + mt * 16 + g + hf * 8;
                int col = bn + wn + nt * 8 + tg * 2;
                float v0 = c[mt][nt][hf * 2], v1 = c[mt][nt][hf * 2 + 1];
                int b = row >> 10, t = row & 1023;
                if (z == 0) {
                    v0 = (v0 + bq[col]) * 0.125f;
                    v1 = (v1 + bq[col + 1]) * 0.125f;
                    int h = col >> 6, d = col & 63;
                    *(float2*)&g_qf[((size_t)(b * HH + h) * TT + t) * HD + d] = make_float2(v0, v1);
                } else if (z == 1) {
                    *(float2*)&kout[((size_t)b * SF + SC + t) * DD + col] = make_float2(v0, v1);
                } else {
                    v0 += bv[col]; v1 += bv[col + 1];
                    *(float2*)&vout[((size_t)b * SF + SC + t) * DD + col] = make_float2(v0, v1);
                }
            }
}

__global__ __launch_bounds__(256) void gemm_o(const float* __restrict__ bo,
                                              float* __restrict__ out) {
    const int bm = blockIdx.y * 128, bn = blockIdx.x * 128;
    float c[4][4][4];
    gemm_core(g_ah, g_al, g_wth + 3ull * DD * DD, g_wtl + 3ull * DD * DD, bm, bn, c);

    const int lane = threadIdx.x & 31, wid = threadIdx.x >> 5;
    const int wm = (wid & 1) * 64, wn = (wid >> 1) * 32;
    const int g = lane >> 2, tg = lane & 3;

    #pragma unroll
    for (int mt = 0; mt < 4; mt++)
        #pragma unroll
        for (int nt = 0; nt < 4; nt++)
            #pragma unroll
            for (int hf = 0; hf < 2; hf++) {
                int row = bm + wm + mt * 16 + g + hf * 8;
                int col = bn + wn + nt * 8 + tg * 2;
                float v0 = c[mt][nt][hf * 2] + bo[col];
                float v1 = c[mt][nt][hf * 2 + 1] + bo[col + 1];
                *(float2*)&out[(size_t)row * DD + col] = make_float2(v0, v1);
            }
}

// ---------------- FlashAttention-2 with split-bf16 HMMA ----------------------
__global__ __launch_bounds__(128) void attn_mma() {
    __shared__ __align__(16) bf16 Ksh[64][72];
    __shared__ __align__(16) bf16 Ksl[64][72];
    __shared__ __align__(16) bf16 Vsh[64][72];
    __shared__ __align__(16) bf16 Vsl[64][72];

    const int tid = threadIdx.x, lane = tid & 31, wid = tid >> 5;
    const int qi = blockIdx.x, h = blockIdx.y, b = blockIdx.z;
    const int qbase = qi * 64;
    const int g = lane >> 2, tg = lane & 3;
    const int ar = lane & 15, akk = (lane >> 4) * 8;
    const int br = (lane & 7) + ((lane >> 4) << 3), bkk = ((lane >> 3) & 1) * 8;

    uint32_t qfh[4][4], qfl[4][4];
    {
        size_t qoff = ((size_t)(b * HH + h) * TT + qbase) * HD;
        #pragma unroll
        for (int p = 0; p < 4; p++) {
            int idx = p * 1024 + tid * 8;
            int r = idx >> 6, cc = idx & 63;
            *(uint4*)&Ksh[r][cc] = *(const uint4*)&g_qh[qoff + (size_t)r * HD + cc];
        }
        __syncthreads();
        #pragma unroll
        for (int kc = 0; kc < 4; kc++)
            ldsm4(qfh[kc], &Ksh[wid * 16 + ar][kc * 16 + akk]);
        __syncthreads();
        #pragma unroll
        for (int p = 0; p < 4; p++) {
            int idx = p * 1024 + tid * 8;
            int r = idx >> 6, cc = idx & 63;
            *(uint4*)&Ksh[r][cc] = *(const uint4*)&g_ql[qoff + (size_t)r * HD + cc];
        }
        __syncthreads();
        #pragma unroll
        for (int kc = 0; kc < 4; kc++)
            ldsm4(qfl[kc], &Ksh[wid * 16 + ar][kc * 16 + akk]);
    }

    float o[8][4];
    #pragma unroll
    for (int dt = 0; dt < 8; dt++)
        #pragma unroll
        for (int e = 0; e < 4; e++) o[dt][e] = 0.0f;
    float m0 = -1e30f, m1 = -1e30f, l0 = 0.0f, l1 = 0.0f;

    const size_t kbase = (size_t)(b * HH + h) * SF * HD;
    const size_t vbase = (size_t)(b * HH + h) * HD * SF;

    for (int si = 0; si < 64; si++) {
        if (si > qi && si < 16) continue;   // fully-masked tile
        const int sbase = si * 64;

        __syncthreads();
        #pragma unroll
        for (int p = 0; p < 4; p++) {
            int idx = p * 1024 + tid * 8;
            int r = idx >> 6, cc = idx & 63;
            *(uint4*)&Ksh[r][cc] = *(const uint4*)&g_kh[kbase + (size_t)(sbase + r) * HD + cc];
            *(uint4*)&Ksl[r][cc] = *(const uint4*)&g_kl[kbase + (size_t)(sbase + r) * HD + cc];
            *(uint4*)&Vsh[r][cc] = *(const uint4*)&g_vth[vbase + (size_t)r * SF + sbase + cc];
            *(uint4*)&Vsl[r][cc] = *(const uint4*)&g_vtl[vbase + (size_t)r * SF + sbase + cc];
        }
        __syncthreads();

        float s[8][4];
        #pragma unroll
        for (int nt = 0; nt < 8; nt++)
            #pragma unroll
            for (int e = 0; e < 4; e++) s[nt][e] = 0.0f;

        #pragma unroll
        for (int kc = 0; kc < 4; kc++) {
            uint32_t bh[4][4], bl[4][4];
            #pragma unroll
            for (int np = 0; np < 4; np++) {
                ldsm4(bh[np], &Ksh[np * 16 + br][kc * 16 + bkk]);
                ldsm4(bl[np], &Ksl[np * 16 + br][kc * 16 + bkk]);
            }
            #pragma unroll
            for (int nt = 0; nt < 8; nt++) {
                int np = nt >> 1, pi = (nt & 1) * 2;
                mma16816(s[nt], qfh[kc], bh[np][pi], bh[np][pi + 1]);
                mma16816(s[nt], qfl[kc], bh[np][pi], bh[np][pi + 1]);
                mma16816(s[nt], qfh[kc], bl[np][pi], bl[np][pi + 1]);
            }
        }

        if (si == qi) {
            #pragma unroll
            for (int nt = 0; nt < 8; nt++)
                #pragma unroll
                for (int e = 0; e < 4; e++) {
                    int row = wid * 16 + g + (e >> 1) * 8;
                    int col = nt * 8 + tg * 2 + (e & 1);
                    if (col > row) s[nt][e] = -1e30f;
                }
        }

        float mt0 = -1e30f, mt1 = -1e30f;
        #pragma unroll
        for (int nt = 0; nt < 8; nt++) {
            mt0 = fmaxf(mt0, fmaxf(s[nt][0], s[nt][1]));
            mt1 = fmaxf(mt1, fmaxf(s[nt][2], s[nt][3]));
        }
        mt0 = fmaxf(mt0, __shfl_xor_sync(0xffffffffu, mt0, 1));
        mt0 = fmaxf(mt0, __shfl_xor_sync(0xffffffffu, mt0, 2));
        mt1 = fmaxf(mt1, __shfl_xor_sync(0xffffffffu, mt1, 1));
        mt1 = fmaxf(mt1, __shfl_xor_sync(0xffffffffu, mt1, 2));

        float mn0 = fmaxf(m0, mt0), mn1 = fmaxf(m1, mt1);
        float a0 = __expf(m0 - mn0), a1 = __expf(m1 - mn1);
        m0 = mn0; m1 = mn1;

        float rs0 = 0.0f, rs1 = 0.0f;
        #pragma unroll
        for (int nt = 0; nt < 8; nt++) {
            s[nt][0] = __expf(s[nt][0] - mn0); rs0 += s[nt][0];
            s[nt][1] = __expf(s[nt][1] - mn0); rs0 += s[nt][1];
            s[nt][2] = __expf(s[nt][2] - mn1); rs1 += s[nt][2];
            s[nt][3] = __expf(s[nt][3] - mn1); rs1 += s[nt][3];
        }
        rs0 += __shfl_xor_sync(0xffffffffu, rs0, 1);
        rs0 += __shfl_xor_sync(0xffffffffu, rs0, 2);
        rs1 += __shfl_xor_sync(0xffffffffu, rs1, 1);
        rs1 += __shfl_xor_sync(0xffffffffu, rs1, 2);
        l0 = l0 * a0 + rs0;
        l1 = l1 * a1 + rs1;

        #pragma unroll
        for (int dt = 0; dt < 8; dt++) {
            o[dt][0] *= a0; o[dt][1] *= a0;
            o[dt][2] *= a1; o[dt][3] *= a1;
        }

        #pragma unroll
        for (int kc = 0; kc < 4; kc++) {
            uint32_t aph[4], apl[4];
            split_pack(s[2 * kc][0],     s[2 * kc][1],     aph[0], apl[0]);
            split_pack(s[2 * kc][2],     s[2 * kc][3],     aph[1], apl[1]);
            split_pack(s[2 * kc + 1][0], s[2 * kc + 1][1], aph[2], apl[2]);
            split_pack(s[2 * kc + 1][2], s[2 * kc + 1][3], aph[3], apl[3]);

            uint32_t vh[4][4], vl[4][4];
            #pragma unroll
            for (int np = 0; np < 4; np++) {
                ldsm4(vh[np], &Vsh[np * 16 + br][kc * 16 + bkk]);
                ldsm4(vl[np], &Vsl[np * 16 + br][kc * 16 + bkk]);
            }
            #pragma unroll
            for (int dt = 0; dt < 8; dt++) {
                int np = dt >> 1, pi = (dt & 1) * 2;
                mma16816(o[dt], aph, vh[np][pi], vh[np][pi + 1]);
                mma16816(o[dt], apl, vh[np][pi], vh[np][pi + 1]);
                mma16816(o[dt], aph, vl[np][pi], vl[np][pi + 1]);
            }
        }
    }

    float inv0 = 1.0f / l0, inv1 = 1.0f / l1;
    int t0 = qbase + wid * 16 + g;
    int t1 = t0 + 8;
    #pragma unroll
    for (int dt = 0; dt < 8; dt++) {
        int d = dt * 8 + tg * 2;
        size_t off0 = ((size_t)b * TT + t0) * DD + h * HD + d;
        size_t off1 = ((size_t)b * TT + t1) * DD + h * HD + d;
        bf162 H, L;
        split1(o[dt][0] * inv0, H.x, L.x);
        split1(o[dt][1] * inv0, H.y, L.y);
        *reinterpret_cast<bf162*>(&g_ah[off0]) = H;
        *reinterpret_cast<bf162*>(&g_al[off0]) = L;
        split1(o[dt][2] * inv1, H.x, L.x);
        split1(o[dt][3] * inv1, H.y, L.y);
        *reinterpret_cast<bf162*>(&g_ah[off1]) = H;
        *reinterpret_cast<bf162*>(&g_al[off1]) = L;
    }
}

// ---------------------------------------------------------------------------
extern "C" void kernel_launch(void* const* d_in, const int* in_sizes, int n_in,
                              void* d_out, int out_size) {
    const float* x  = (const float*)d_in[0];
    const float* kc = (const float*)d_in[1];
    const float* vc = (const float*)d_in[2];
    const float* bq = (const float*)d_in[4];
    const float* bv = (const float*)d_in[7];
    const float* bo = (const float*)d_in[9];

    float* out  = (float*)d_out;
    float* kout = out + (size_t)BB * TT * DD;
    float* vout = kout + (size_t)BB * SF * DD;

    conv_x<<<BB * TT * DD / 1024, 256>>>((const float4*)x);
    conv_w<<<dim3(32, 32, 4), dim3(32, 8)>>>(
        (const float*)d_in[3], (const float*)d_in[5],
        (const float*)d_in[6], (const float*)d_in[8]);

    conv_k<<<BB * SC, 256>>>((const float4*)kc, (size_t)SC * 256, 0, SC, (float4*)kout);
    conv_vt<<<dim3(SC / 32, HH * 2, BB), dim3(32, 8)>>>(vc, (size_t)SC * DD, 0, SC, vout);

    gemm_qkv<<<dim3(8, 32, 3), 256>>>(bq, bv, kout, vout);

    conv_q<<<BB * HH * TT * HD / 1024, 256>>>();
    conv_k<<<BB * TT, 256>>>((const float4*)kout + (size_t)SC * 256,
                             (size_t)SF * 256, SC, TT, nullptr);
    conv_vt<<<dim3(TT / 32, HH * 2, BB), dim3(32, 8)>>>(
        vout + (size_t)SC * DD, (size_t)SF * DD, SC, TT, nullptr);

    attn_mma<<<dim3(16, HH, BB), 128>>>();

    gemm_o<<<dim3(8, 32), 256>>>(bo, out);
}